// round 2
// baseline (speedup 1.0000x reference)
#include <cuda_runtime.h>
#include <cuda_bf16.h>
#include <cstdint>

// ============================================================================
// RBF kernel: out[m][n] = exp(-(||x_m||^2 + ||y_n||^2 - 2 x_m.y_n)), gamma=1
// x, y: 8192 x 64 fp32.  out: 8192 x 8192 fp32.
//
// Path: mma.sync.m16n8k16 bf16 (PTX target is compute_100: no tcgen05).
// Accuracy: hi/lo bf16 split, 3 GEMMs (hh + hl + lh), fp32 accumulate.
// Epilogue: fused, denormal-exact exp via ex2 + non-FTZ scale multiply.
// ============================================================================

#define NROWS 8192
#define DDIM  64

__device__ __nv_bfloat16 g_xhi[NROWS * DDIM];
__device__ __nv_bfloat16 g_xlo[NROWS * DDIM];
__device__ __nv_bfloat16 g_yhi[NROWS * DDIM];
__device__ __nv_bfloat16 g_ylo[NROWS * DDIM];
__device__ float g_x2[NROWS];
__device__ float g_y2[NROWS];

__device__ __forceinline__ uint32_t smem_u32(const void* p) {
    uint32_t a;
    asm("{ .reg .u64 t; cvta.to.shared.u64 t, %1; cvt.u32.u64 %0, t; }"
        : "=r"(a) : "l"(p));
    return a;
}

#define SWZ128(off) ((off) ^ (((off) >> 3) & 0x70))

#define LDSM_X4(r0, r1, r2, r3, addr)                                          \
    asm volatile("ldmatrix.sync.aligned.m8n8.x4.shared.b16 {%0,%1,%2,%3}, [%4];" \
                 : "=r"(r0), "=r"(r1), "=r"(r2), "=r"(r3) : "r"(addr))

#define MMA_BF16(c, a, b0, b1)                                                 \
    asm volatile(                                                              \
        "mma.sync.aligned.m16n8k16.row.col.f32.bf16.bf16.f32 "                 \
        "{%0,%1,%2,%3}, {%4,%5,%6,%7}, {%8,%9}, {%0,%1,%2,%3};"                \
        : "+f"((c)[0]), "+f"((c)[1]), "+f"((c)[2]), "+f"((c)[3])               \
        : "r"((a)[0]), "r"((a)[1]), "r"((a)[2]), "r"((a)[3]),                  \
          "r"(b0), "r"(b1))

// ---------------------------------------------------------------------------
// Prologue: bf16 hi/lo split + row norms. One warp per row.
// ---------------------------------------------------------------------------
__global__ void rbf_split(const float* __restrict__ x,
                          const float* __restrict__ y) {
    int warp = (blockIdx.x * blockDim.x + threadIdx.x) >> 5;
    int lane = threadIdx.x & 31;
    if (warp >= 2 * NROWS) return;
    bool isx = warp < NROWS;
    int row = isx ? warp : warp - NROWS;
    const float* src = (isx ? x : y) + (size_t)row * DDIM;
    __nv_bfloat16* hi = (isx ? g_xhi : g_yhi) + (size_t)row * DDIM;
    __nv_bfloat16* lo = (isx ? g_xlo : g_ylo) + (size_t)row * DDIM;
    float s = 0.0f;
#pragma unroll
    for (int i = 0; i < 2; i++) {
        int c = lane + i * 32;
        float v = src[c];
        __nv_bfloat16 h = __float2bfloat16(v);
        float hv = __bfloat162float(h);
        hi[c] = h;
        lo[c] = __float2bfloat16(v - hv);
        s = fmaf(v, v, s);
    }
#pragma unroll
    for (int o = 16; o; o >>= 1) s += __shfl_xor_sync(0xFFFFFFFFu, s, o);
    if (lane == 0) (isx ? g_x2 : g_y2)[row] = s;
}

// ---------------------------------------------------------------------------
// Main: 128(m) x 128(n) tile per CTA, 256 threads = 8 warps (4m x 2n),
// warp tile 32(m) x 64(n), mma.m16n8k16.
// ---------------------------------------------------------------------------
// SMEM layout (tiles 1024-aligned, 128 B rows for SW128-style swizzle):
#define SM_X2   0                       // 128 floats
#define SM_Y2   512                     // 128 floats
#define SM_XHI  1024
#define SM_XLO  (SM_XHI + 16384)
#define SM_YHI  (SM_XLO + 16384)
#define SM_YLO  (SM_YHI + 16384)
#define SMEM_TOTAL (SM_YLO + 16384)     // 66560 B

__global__ void __launch_bounds__(256)
rbf_main(float* __restrict__ out) {
    extern __shared__ char smem[];
    const uint32_t sb = smem_u32(smem);
    const int tid = threadIdx.x;
    const int wid = tid >> 5;
    const int lane = tid & 31;
    const int warp_m = wid & 3;          // 0..3 -> m offset *32
    const int warp_n = wid >> 2;         // 0..1 -> n offset *64
    const int m_base = blockIdx.x << 7;
    const int n_base = blockIdx.y << 7;

    // ---- Load tiles (each tile = 16 KB contiguous gmem), swizzled 16B chunks
    {
        const uint4* xh = (const uint4*)(g_xhi + (size_t)m_base * DDIM);
        const uint4* xl = (const uint4*)(g_xlo + (size_t)m_base * DDIM);
        const uint4* yh = (const uint4*)(g_yhi + (size_t)n_base * DDIM);
        const uint4* yl = (const uint4*)(g_ylo + (size_t)n_base * DDIM);
#pragma unroll
        for (int idx = tid; idx < 1024; idx += 256) {
            uint32_t sw = SWZ128((uint32_t)idx * 16u);
            *(uint4*)(smem + SM_XHI + sw) = xh[idx];
            *(uint4*)(smem + SM_XLO + sw) = xl[idx];
            *(uint4*)(smem + SM_YHI + sw) = yh[idx];
            *(uint4*)(smem + SM_YLO + sw) = yl[idx];
        }
    }
    if (tid < 128) ((float*)(smem + SM_X2))[tid] = g_x2[m_base + tid];
    else           ((float*)(smem + SM_Y2))[tid - 128] = g_y2[n_base + tid - 128];
    __syncthreads();

    // ---- Accumulators: c[mt][np][sub][4]  (2 m-tiles, 4 n-pairs, 2 n-subtiles)
    float c[2][4][2][4];
#pragma unroll
    for (int a = 0; a < 2; a++)
#pragma unroll
        for (int b = 0; b < 4; b++)
#pragma unroll
            for (int d = 0; d < 2; d++)
#pragma unroll
                for (int e = 0; e < 4; e++) c[a][b][d][e] = 0.0f;

    // ldmatrix lane-address components
    const int grp = lane >> 3, rl = lane & 7;
    // A (x tile): tiles ordered (m0-7,k0-7),(m8-15,k0-7),(m0-7,k8-15),(m8-15,k8-15)
    const uint32_t a_row  = (uint32_t)(warp_m * 32 + (grp & 1) * 8 + rl);
    const uint32_t a_koff = (uint32_t)((grp >> 1) * 8);
    // B (y tile): tiles ordered (n0-7,k0-7),(n0-7,k8-15),(n8-15,k0-7),(n8-15,k8-15)
    const uint32_t b_row  = (uint32_t)(warp_n * 64 + ((grp >> 1) & 1) * 8 + rl);
    const uint32_t b_koff = (uint32_t)((grp & 1) * 8);

#pragma unroll
    for (int ks = 0; ks < 4; ks++) {
        const uint32_t k = (uint32_t)(ks * 16);
        uint32_t ah[2][4], al[2][4];
#pragma unroll
        for (int mt = 0; mt < 2; mt++) {
            uint32_t off = (a_row + (uint32_t)(mt * 16)) * 128u + (k + a_koff) * 2u;
            uint32_t sw = SWZ128(off);
            LDSM_X4(ah[mt][0], ah[mt][1], ah[mt][2], ah[mt][3], sb + SM_XHI + sw);
            LDSM_X4(al[mt][0], al[mt][1], al[mt][2], al[mt][3], sb + SM_XLO + sw);
        }
#pragma unroll
        for (int np = 0; np < 4; np++) {
            uint32_t off = (b_row + (uint32_t)(np * 16)) * 128u + (k + b_koff) * 2u;
            uint32_t sw = SWZ128(off);
            uint32_t bh[4], bl[4];
            LDSM_X4(bh[0], bh[1], bh[2], bh[3], sb + SM_YHI + sw);
            LDSM_X4(bl[0], bl[1], bl[2], bl[3], sb + SM_YLO + sw);
#pragma unroll
            for (int mt = 0; mt < 2; mt++) {
                MMA_BF16(c[mt][np][0], ah[mt], bh[0], bh[1]);   // hi*hi
                MMA_BF16(c[mt][np][1], ah[mt], bh[2], bh[3]);
                MMA_BF16(c[mt][np][0], ah[mt], bl[0], bl[1]);   // hi*lo
                MMA_BF16(c[mt][np][1], ah[mt], bl[2], bl[3]);
                MMA_BF16(c[mt][np][0], al[mt], bh[0], bh[1]);   // lo*hi
                MMA_BF16(c[mt][np][1], al[mt], bh[2], bh[3]);
            }
        }
    }

    // ---- Epilogue: sq = x2 + y2 - 2*xy; out = exp(-sq), denormal-exact.
    const float* x2s = (const float*)(smem + SM_X2);
    const float* y2s = (const float*)(smem + SM_Y2);
    const int r_loc0 = warp_m * 32 + (lane >> 2);
    const int c_loc0 = warp_n * 64 + (lane & 3) * 2;

#pragma unroll
    for (int mt = 0; mt < 2; mt++) {
#pragma unroll
        for (int rh = 0; rh < 2; rh++) {
            const int row = r_loc0 + mt * 16 + rh * 8;
            const float x2v = x2s[row];
            float* orow = out + (size_t)(m_base + row) * NROWS + n_base;
#pragma unroll
            for (int np = 0; np < 4; np++) {
#pragma unroll
                for (int sub = 0; sub < 2; sub++) {
                    const int col = c_loc0 + np * 16 + sub * 8;
                    const float d0 = c[mt][np][sub][rh * 2 + 0];
                    const float d1 = c[mt][np][sub][rh * 2 + 1];
                    float sq0 = fmaxf(x2s[row] + y2s[col]     - 2.0f * d0, 0.0f);
                    float sq1 = fmaxf(x2v      + y2s[col + 1] - 2.0f * d1, 0.0f);
                    // exp(-sq) = 2^(64 - sq*log2e) * 2^-64; final mul is a
                    // forced non-FTZ mul.f32 so fp32 denormals are exact.
                    float u0 = fmaf(sq0, -1.4426950408889634f, 64.0f);
                    float u1 = fmaf(sq1, -1.4426950408889634f, 64.0f);
                    float e0, e1, r0, r1;
                    asm("ex2.approx.f32 %0, %1;" : "=f"(e0) : "f"(u0));
                    asm("ex2.approx.f32 %0, %1;" : "=f"(e1) : "f"(u1));
                    asm("mul.f32 %0, %1, %2;"
                        : "=f"(r0) : "f"(e0), "f"(5.421010862427522e-20f));
                    asm("mul.f32 %0, %1, %2;"
                        : "=f"(r1) : "f"(e1), "f"(5.421010862427522e-20f));
                    float2 st = make_float2(r0, r1);
                    *(float2*)(orow + col) = st;
                }
            }
        }
    }
}

// ---------------------------------------------------------------------------
extern "C" void kernel_launch(void* const* d_in, const int* in_sizes, int n_in,
                              void* d_out, int out_size) {
    const float* x = (const float*)d_in[0];
    const float* y = (const float*)d_in[1];
    float* out = (float*)d_out;

    cudaFuncSetAttribute(rbf_main,
                         cudaFuncAttributeMaxDynamicSharedMemorySize,
                         SMEM_TOTAL);

    rbf_split<<<2048, 256>>>(x, y);

    dim3 grid(NROWS / 128, NROWS / 128);  // 64 x 64 tiles
    rbf_main<<<grid, 256, SMEM_TOTAL>>>(out);
}

// round 4
// speedup vs baseline: 1.0673x; 1.0673x over previous
#include <cuda_runtime.h>
#include <cuda_bf16.h>
#include <cstdint>

// ============================================================================
// RBF kernel: out[m][n] = exp(-(||x_m||^2 + ||y_n||^2 - 2 x_m.y_n)), gamma=1
// x, y: 8192 x 64 fp32.  out: 8192 x 8192 fp32.
//
// mma.sync.m16n8k16 bf16, hi/lo split (3 GEMMs), fused denormal-exact exp.
// R3: 64x64 warp tiles (fewer LDSM per MAC) + y-column permutation so the
// epilogue issues coalesced STG.128 instead of scattered STG.64.
// ============================================================================

#define NROWS 8192
#define DDIM  64

__device__ __nv_bfloat16 g_xhi[NROWS * DDIM];
__device__ __nv_bfloat16 g_xlo[NROWS * DDIM];
__device__ __nv_bfloat16 g_yhi[NROWS * DDIM];
__device__ __nv_bfloat16 g_ylo[NROWS * DDIM];
__device__ float g_x2[NROWS];
__device__ float g_y2[NROWS];

__device__ __forceinline__ uint32_t smem_u32(const void* p) {
    uint32_t a;
    asm("{ .reg .u64 t; cvta.to.shared.u64 t, %1; cvt.u32.u64 %0, t; }"
        : "=r"(a) : "l"(p));
    return a;
}

#define SWZ128(off) ((off) ^ (((off) >> 3) & 0x70))

// Column permutation within each 16-col group: logical col l sits at physical
// accumulator col perm16(l).  Thread q (= lane&3) then owns logical columns
// 4q..4q+3 -> float4 stores.
#define PERM16(v) ((((v) >> 1) & 1) << 3 | (((v) >> 2) & 3) << 1 | ((v) & 1))

#define LDSM_X4(r0, r1, r2, r3, addr)                                          \
    asm volatile("ldmatrix.sync.aligned.m8n8.x4.shared.b16 {%0,%1,%2,%3}, [%4];" \
                 : "=r"(r0), "=r"(r1), "=r"(r2), "=r"(r3) : "r"(addr))

#define MMA_BF16(c, a, b0, b1)                                                 \
    asm volatile(                                                              \
        "mma.sync.aligned.m16n8k16.row.col.f32.bf16.bf16.f32 "                 \
        "{%0,%1,%2,%3}, {%4,%5,%6,%7}, {%8,%9}, {%0,%1,%2,%3};"                \
        : "+f"((c)[0]), "+f"((c)[1]), "+f"((c)[2]), "+f"((c)[3])               \
        : "r"((a)[0]), "r"((a)[1]), "r"((a)[2]), "r"((a)[3]),                  \
          "r"(b0), "r"(b1))

// ---------------------------------------------------------------------------
// Prologue: bf16 hi/lo split + row norms. One warp per row.
// ---------------------------------------------------------------------------
__global__ void rbf_split(const float* __restrict__ x,
                          const float* __restrict__ y) {
    int warp = (blockIdx.x * blockDim.x + threadIdx.x) >> 5;
    int lane = threadIdx.x & 31;
    if (warp >= 2 * NROWS) return;
    bool isx = warp < NROWS;
    int row = isx ? warp : warp - NROWS;
    const float* src = (isx ? x : y) + (size_t)row * DDIM;
    __nv_bfloat16* hi = (isx ? g_xhi : g_yhi) + (size_t)row * DDIM;
    __nv_bfloat16* lo = (isx ? g_xlo : g_ylo) + (size_t)row * DDIM;
    float s = 0.0f;
#pragma unroll
    for (int i = 0; i < 2; i++) {
        int c = lane + i * 32;
        float v = src[c];
        __nv_bfloat16 h = __float2bfloat16(v);
        float hv = __bfloat162float(h);
        hi[c] = h;
        lo[c] = __float2bfloat16(v - hv);
        s = fmaf(v, v, s);
    }
#pragma unroll
    for (int o = 16; o; o >>= 1) s += __shfl_xor_sync(0xFFFFFFFFu, s, o);
    if (lane == 0) (isx ? g_x2 : g_y2)[row] = s;
}

// ---------------------------------------------------------------------------
// Main: 128x128 tile per CTA, 128 threads = 4 warps (2m x 2n), warp tile 64x64.
// ---------------------------------------------------------------------------
#define SM_X2   0                       // 128 floats
#define SM_Y2   512                     // 128 floats (logical order)
#define SM_XHI  1024
#define SM_XLO  (SM_XHI + 16384)
#define SM_YHI  (SM_XLO + 16384)
#define SM_YLO  (SM_YHI + 16384)
#define SMEM_TOTAL (SM_YLO + 16384)     // 66560 B

__global__ void __launch_bounds__(128)
rbf_main(float* __restrict__ out) {
    extern __shared__ char smem[];
    const uint32_t sb = smem_u32(smem);
    const int tid = threadIdx.x;
    const int wid = tid >> 5;
    const int lane = tid & 31;
    const int warp_m = wid & 1;          // m offset *64
    const int warp_n = wid >> 1;         // n offset *64
    const int m_base = blockIdx.x << 7;
    const int n_base = blockIdx.y << 7;

    // ---- Tile fill. x tiles straight; y tiles row-permuted (PERM16 within
    // each 16-row group) so accumulator columns come out store-coalesced.
    {
        const uint4* xh = (const uint4*)(g_xhi + (size_t)m_base * DDIM);
        const uint4* xl = (const uint4*)(g_xlo + (size_t)m_base * DDIM);
        const uint4* yh = (const uint4*)(g_yhi + (size_t)n_base * DDIM);
        const uint4* yl = (const uint4*)(g_ylo + (size_t)n_base * DDIM);
#pragma unroll
        for (int idx = tid; idx < 1024; idx += 128) {
            uint32_t sw = SWZ128((uint32_t)idx * 16u);
            *(uint4*)(smem + SM_XHI + sw) = xh[idx];
            *(uint4*)(smem + SM_XLO + sw) = xl[idx];
            uint32_t row = (uint32_t)idx >> 3, cc = (uint32_t)idx & 7;
            uint32_t prow = (row & 0x70u) | (uint32_t)PERM16(row & 15u);
            uint32_t dsw = SWZ128(prow * 128u + cc * 16u);
            *(uint4*)(smem + SM_YHI + dsw) = yh[idx];
            *(uint4*)(smem + SM_YLO + dsw) = yl[idx];
        }
    }
    ((float*)(smem + SM_X2))[tid] = g_x2[m_base + tid];
    ((float*)(smem + SM_Y2))[tid] = g_y2[n_base + tid];
    __syncthreads();

    // ---- Accumulators: c[mt 0..3][np 0..3][sub 0..1][4]
    float c[4][4][2][4];
#pragma unroll
    for (int a = 0; a < 4; a++)
#pragma unroll
        for (int b = 0; b < 4; b++)
#pragma unroll
            for (int d = 0; d < 2; d++)
#pragma unroll
                for (int e = 0; e < 4; e++) c[a][b][d][e] = 0.0f;

    const int grp = lane >> 3, rl = lane & 7;
    const uint32_t a_row  = (uint32_t)(warp_m * 64 + (grp & 1) * 8 + rl);
    const uint32_t a_koff = (uint32_t)((grp >> 1) * 8);
    const uint32_t b_row  = (uint32_t)(warp_n * 64 + ((grp >> 1) & 1) * 8 + rl);
    const uint32_t b_koff = (uint32_t)((grp & 1) * 8);

#pragma unroll
    for (int ks = 0; ks < 4; ks++) {
        const uint32_t k = (uint32_t)(ks * 16);
        uint32_t ah[4][4], al[4][4];
#pragma unroll
        for (int mt = 0; mt < 4; mt++) {
            uint32_t off = (a_row + (uint32_t)(mt * 16)) * 128u + (k + a_koff) * 2u;
            uint32_t sw = SWZ128(off);
            LDSM_X4(ah[mt][0], ah[mt][1], ah[mt][2], ah[mt][3], sb + SM_XHI + sw);
            LDSM_X4(al[mt][0], al[mt][1], al[mt][2], al[mt][3], sb + SM_XLO + sw);
        }
#pragma unroll
        for (int np = 0; np < 4; np++) {
            uint32_t off = (b_row + (uint32_t)(np * 16)) * 128u + (k + b_koff) * 2u;
            uint32_t sw = SWZ128(off);
            uint32_t bh[4], bl[4];
            LDSM_X4(bh[0], bh[1], bh[2], bh[3], sb + SM_YHI + sw);
            LDSM_X4(bl[0], bl[1], bl[2], bl[3], sb + SM_YLO + sw);
#pragma unroll
            for (int mt = 0; mt < 4; mt++) {
                MMA_BF16(c[mt][np][0], ah[mt], bh[0], bh[1]);   // hi*hi
                MMA_BF16(c[mt][np][1], ah[mt], bh[2], bh[3]);
                MMA_BF16(c[mt][np][0], ah[mt], bl[0], bl[1]);   // hi*lo
                MMA_BF16(c[mt][np][1], ah[mt], bl[2], bl[3]);
                MMA_BF16(c[mt][np][0], al[mt], bh[0], bh[1]);   // lo*hi
                MMA_BF16(c[mt][np][1], al[mt], bh[2], bh[3]);
            }
        }
    }

    // ---- Epilogue: thanks to PERM16, thread q owns logical cols 4q..4q+3 in
    // each 16-col group: sub0 regs -> cols 4q,4q+1; sub1 regs -> 4q+2,4q+3.
    const float* x2s = (const float*)(smem + SM_X2);
    const float* y2s = (const float*)(smem + SM_Y2);
    const int q = lane & 3;
    float4 y2q[4];
#pragma unroll
    for (int np = 0; np < 4; np++)
        y2q[np] = *(const float4*)(y2s + warp_n * 64 + np * 16 + 4 * q);

    const float NL2E = -1.4426950408889634f;
    const float SC64 = 5.421010862427522e-20f;   // 2^-64

#pragma unroll
    for (int mt = 0; mt < 4; mt++) {
#pragma unroll
        for (int rh = 0; rh < 2; rh++) {
            const int row = warp_m * 64 + mt * 16 + rh * 8 + (lane >> 2);
            const float x2v = x2s[row];
            float* orow = out + (size_t)(m_base + row) * NROWS
                              + (size_t)(n_base + warp_n * 64);
#pragma unroll
            for (int np = 0; np < 4; np++) {
                float d0 = c[mt][np][0][rh * 2 + 0];
                float d1 = c[mt][np][0][rh * 2 + 1];
                float d2 = c[mt][np][1][rh * 2 + 0];
                float d3 = c[mt][np][1][rh * 2 + 1];
                float s0 = fmaxf(x2v + y2q[np].x - 2.0f * d0, 0.0f);
                float s1 = fmaxf(x2v + y2q[np].y - 2.0f * d1, 0.0f);
                float s2 = fmaxf(x2v + y2q[np].z - 2.0f * d2, 0.0f);
                float s3 = fmaxf(x2v + y2q[np].w - 2.0f * d3, 0.0f);
                // exp(-s) = 2^(64 - s*log2e) * 2^-64; final mul is a forced
                // non-FTZ mul.f32 so fp32 denormals come out exact.
                float u0 = fmaf(s0, NL2E, 64.0f), u1 = fmaf(s1, NL2E, 64.0f);
                float u2 = fmaf(s2, NL2E, 64.0f), u3 = fmaf(s3, NL2E, 64.0f);
                float e0, e1, e2, e3;
                asm("ex2.approx.f32 %0, %1;" : "=f"(e0) : "f"(u0));
                asm("ex2.approx.f32 %0, %1;" : "=f"(e1) : "f"(u1));
                asm("ex2.approx.f32 %0, %1;" : "=f"(e2) : "f"(u2));
                asm("ex2.approx.f32 %0, %1;" : "=f"(e3) : "f"(u3));
                float4 r;
                asm("mul.f32 %0, %1, %2;" : "=f"(r.x) : "f"(e0), "f"(SC64));
                asm("mul.f32 %0, %1, %2;" : "=f"(r.y) : "f"(e1), "f"(SC64));
                asm("mul.f32 %0, %1, %2;" : "=f"(r.z) : "f"(e2), "f"(SC64));
                asm("mul.f32 %0, %1, %2;" : "=f"(r.w) : "f"(e3), "f"(SC64));
                *(float4*)(orow + np * 16 + 4 * q) = r;
            }
        }
    }
}

// ---------------------------------------------------------------------------
extern "C" void kernel_launch(void* const* d_in, const int* in_sizes, int n_in,
                              void* d_out, int out_size) {
    const float* x = (const float*)d_in[0];
    const float* y = (const float*)d_in[1];
    float* out = (float*)d_out;

    cudaFuncSetAttribute(rbf_main,
                         cudaFuncAttributeMaxDynamicSharedMemorySize,
                         SMEM_TOTAL);

    rbf_split<<<2048, 256>>>(x, y);

    dim3 grid(NROWS / 128, NROWS / 128);  // 64 x 64 tiles
    rbf_main<<<grid, 128, SMEM_TOTAL>>>(out);
}